// round 9
// baseline (speedup 1.0000x reference)
#include <cuda_runtime.h>
#include <math.h>
#include <stdint.h>

#define S 2048
#define HID 2048
#define HQ 16
#define HKV 2
#define HD 128
#define G_GRP 8          // HQ / HKV
#define CS 128
#define NC 16            // S / CS
#define WIN 16
#define NBLK 8           // BUDGET / CS
#define ALPHA 0.8f
#define MIXL 0.5f
#define SCALE 0.08838834764831845f  // 128^-0.5
#define NEGV -1000000000.0f

// ---------------- scratch (device globals; no allocation allowed) ----------
// zero-initialized; padding tails are read (as 0.0f) by masked lanes only
__device__ float g_q[S * HQ * HD];            // [s][h*128+d]
__device__ float g_k[S * HKV * HD];           // [s][h*128+d]
__device__ float g_kT[HKV * HD * S + 64];     // [kvh][d][s]  (+pad)
__device__ float g_v[S * HKV * HD + 32 * HKV * HD];  // (+32 pad rows)
__device__ float g_kcmean[HKV * NC * HD];
__device__ float g_kcmax[HKV * NC * HD];
__device__ unsigned g_sel[HKV * S];
__device__ float g_attn[S * HQ * HD];         // [s][h*128+d]

// ---------------- 3xTF32 tensor-core GEMM ----------------------------------
#define GBM 128
#define GBN 128
#define GBK 16
#define ASTR 132
#define BSTR 132

__device__ __forceinline__ uint32_t f2tf32(float f)
{
    uint32_t r;
    asm("cvt.rna.tf32.f32 %0, %1;" : "=r"(r) : "f"(f));
    return r;
}

__device__ __forceinline__ void split_tf32(float x, uint32_t& h, uint32_t& l)
{
    h = f2tf32(x);
    l = f2tf32(x - __uint_as_float(h));
}

__device__ __forceinline__ void mma_tf32(float c[4], const uint32_t a[4], const uint32_t b[2])
{
    asm volatile(
        "mma.sync.aligned.m16n8k8.row.col.f32.tf32.tf32.f32 "
        "{%0,%1,%2,%3}, {%4,%5,%6,%7}, {%8,%9}, {%0,%1,%2,%3};"
        : "+f"(c[0]), "+f"(c[1]), "+f"(c[2]), "+f"(c[3])
        : "r"(a[0]), "r"(a[1]), "r"(a[2]), "r"(a[3]), "r"(b[0]), "r"(b[1]));
}

__global__ __launch_bounds__(256) void gemm_3xtf32(
    const float* __restrict__ A, const float* __restrict__ B,
    const float* __restrict__ bias, float* __restrict__ C,
    int M, int N, int K)
{
    __shared__ uint32_t AsH[GBK][ASTR];
    __shared__ uint32_t AsL[GBK][ASTR];
    __shared__ uint32_t BsH[GBK][BSTR];
    __shared__ uint32_t BsL[GBK][BSTR];

    int tid = threadIdx.x;
    int lane = tid & 31;
    int wid = tid >> 5;
    int wm = (wid & 3) * 32;
    int wn = (wid >> 2) * 64;

    const float* Ab = A + (size_t)blockIdx.y * GBM * K;
    const float* Bb = B + (size_t)blockIdx.x * GBN;

    int ar = tid >> 2;
    int ak = (tid & 3) * 4;
    int bkr = tid >> 5;
    int bn = (tid & 31) * 4;

    float4 ra0, ra1, rb0, rb1;
    ra0 = *(const float4*)(Ab + (size_t)ar * K + ak);
    ra1 = *(const float4*)(Ab + (size_t)(ar + 64) * K + ak);
    rb0 = *(const float4*)(Bb + (size_t)bkr * N + bn);
    rb1 = *(const float4*)(Bb + (size_t)(bkr + 8) * N + bn);

    float acc[2][8][4];
    #pragma unroll
    for (int mt = 0; mt < 2; mt++)
        #pragma unroll
        for (int nt = 0; nt < 8; nt++)
            #pragma unroll
            for (int c = 0; c < 4; c++) acc[mt][nt][c] = 0.f;

    int qrow = lane >> 2;
    int qcol = lane & 3;

    for (int k0 = 0; k0 < K; k0 += GBK) {
        {
            uint32_t h, l;
            split_tf32(ra0.x, h, l); AsH[ak + 0][ar] = h; AsL[ak + 0][ar] = l;
            split_tf32(ra0.y, h, l); AsH[ak + 1][ar] = h; AsL[ak + 1][ar] = l;
            split_tf32(ra0.z, h, l); AsH[ak + 2][ar] = h; AsL[ak + 2][ar] = l;
            split_tf32(ra0.w, h, l); AsH[ak + 3][ar] = h; AsL[ak + 3][ar] = l;
            split_tf32(ra1.x, h, l); AsH[ak + 0][ar + 64] = h; AsL[ak + 0][ar + 64] = l;
            split_tf32(ra1.y, h, l); AsH[ak + 1][ar + 64] = h; AsL[ak + 1][ar + 64] = l;
            split_tf32(ra1.z, h, l); AsH[ak + 2][ar + 64] = h; AsL[ak + 2][ar + 64] = l;
            split_tf32(ra1.w, h, l); AsH[ak + 3][ar + 64] = h; AsL[ak + 3][ar + 64] = l;
            split_tf32(rb0.x, h, l); BsH[bkr][bn + 0] = h; BsL[bkr][bn + 0] = l;
            split_tf32(rb0.y, h, l); BsH[bkr][bn + 1] = h; BsL[bkr][bn + 1] = l;
            split_tf32(rb0.z, h, l); BsH[bkr][bn + 2] = h; BsL[bkr][bn + 2] = l;
            split_tf32(rb0.w, h, l); BsH[bkr][bn + 3] = h; BsL[bkr][bn + 3] = l;
            split_tf32(rb1.x, h, l); BsH[bkr + 8][bn + 0] = h; BsL[bkr + 8][bn + 0] = l;
            split_tf32(rb1.y, h, l); BsH[bkr + 8][bn + 1] = h; BsL[bkr + 8][bn + 1] = l;
            split_tf32(rb1.z, h, l); BsH[bkr + 8][bn + 2] = h; BsL[bkr + 8][bn + 2] = l;
            split_tf32(rb1.w, h, l); BsH[bkr + 8][bn + 3] = h; BsL[bkr + 8][bn + 3] = l;
        }
        __syncthreads();

        if (k0 + GBK < K) {
            ra0 = *(const float4*)(Ab + (size_t)ar * K + (k0 + GBK) + ak);
            ra1 = *(const float4*)(Ab + (size_t)(ar + 64) * K + (k0 + GBK) + ak);
            rb0 = *(const float4*)(Bb + (size_t)(k0 + GBK + bkr) * N + bn);
            rb1 = *(const float4*)(Bb + (size_t)(k0 + GBK + bkr + 8) * N + bn);
        }

        #pragma unroll
        for (int ks = 0; ks < 2; ks++) {
            int kb = ks * 8;
            uint32_t afH[2][4], afL[2][4];
            #pragma unroll
            for (int mt = 0; mt < 2; mt++) {
                int mb = wm + mt * 16;
                afH[mt][0] = AsH[kb + qcol][mb + qrow];
                afH[mt][1] = AsH[kb + qcol][mb + qrow + 8];
                afH[mt][2] = AsH[kb + qcol + 4][mb + qrow];
                afH[mt][3] = AsH[kb + qcol + 4][mb + qrow + 8];
                afL[mt][0] = AsL[kb + qcol][mb + qrow];
                afL[mt][1] = AsL[kb + qcol][mb + qrow + 8];
                afL[mt][2] = AsL[kb + qcol + 4][mb + qrow];
                afL[mt][3] = AsL[kb + qcol + 4][mb + qrow + 8];
            }
            uint32_t bfH[8][2], bfL[8][2];
            #pragma unroll
            for (int nt = 0; nt < 8; nt++) {
                int nb = wn + nt * 8;
                bfH[nt][0] = BsH[kb + qcol][nb + qrow];
                bfH[nt][1] = BsH[kb + qcol + 4][nb + qrow];
                bfL[nt][0] = BsL[kb + qcol][nb + qrow];
                bfL[nt][1] = BsL[kb + qcol + 4][nb + qrow];
            }
            #pragma unroll
            for (int mt = 0; mt < 2; mt++)
                #pragma unroll
                for (int nt = 0; nt < 8; nt++) {
                    mma_tf32(acc[mt][nt], afL[mt], bfH[nt]);
                    mma_tf32(acc[mt][nt], afH[mt], bfL[nt]);
                    mma_tf32(acc[mt][nt], afH[mt], bfH[nt]);
                }
        }
        __syncthreads();
    }

    #pragma unroll
    for (int mt = 0; mt < 2; mt++) {
        int row0 = blockIdx.y * GBM + wm + mt * 16 + qrow;
        #pragma unroll
        for (int nt = 0; nt < 8; nt++) {
            int col = blockIdx.x * GBN + wn + nt * 8 + qcol * 2;
            float b0 = 0.f, b1 = 0.f;
            if (bias) { b0 = bias[col]; b1 = bias[col + 1]; }
            float2 o0 = make_float2(acc[mt][nt][0] + b0, acc[mt][nt][1] + b1);
            float2 o1 = make_float2(acc[mt][nt][2] + b0, acc[mt][nt][3] + b1);
            *(float2*)(C + (size_t)row0 * N + col) = o0;
            *(float2*)(C + (size_t)(row0 + 8) * N + col) = o1;
        }
    }
}

// ---------------- RoPE -----------------------------------------------------
__global__ void rope_kernel(float* __restrict__ x, const float* __restrict__ cosb,
                            const float* __restrict__ sinb, int H, int stride)
{
    int idx = blockIdx.x * blockDim.x + threadIdx.x;
    if (idx >= S * H * 64) return;
    int d = idx & 63;
    int h = (idx >> 6) % H;
    int s = idx / (64 * H);
    float c0 = cosb[s * HD + d],      s0 = sinb[s * HD + d];
    float c1 = cosb[s * HD + d + 64], s1 = sinb[s * HD + d + 64];
    float* p = x + (size_t)s * stride + h * HD;
    float x0 = p[d], x1 = p[d + 64];
    p[d]      = x0 * c0 - x1 * s0;
    p[d + 64] = x1 * c1 + x0 * s1;
}

// ---------------- K transpose: g_kT[kvh][d][s] = g_k[s][kvh*HD+d] ----------
__global__ __launch_bounds__(256) void transpose_k()
{
    __shared__ float t[32][33];
    int kvh = blockIdx.z;
    int s0 = blockIdx.x * 32, d0 = blockIdx.y * 32;
    int x = threadIdx.x & 31, y0 = threadIdx.x >> 5;   // 8 y-rows
    #pragma unroll
    for (int yy = y0; yy < 32; yy += 8)
        t[yy][x] = g_k[(size_t)(s0 + yy) * (HKV * HD) + kvh * HD + d0 + x];
    __syncthreads();
    #pragma unroll
    for (int yy = y0; yy < 32; yy += 8)
        g_kT[(size_t)kvh * HD * S + (size_t)(d0 + yy) * S + s0 + x] = t[x][yy];
}

// ---------------- per-chunk K stats ----------------------------------------
__global__ void blockstats_kernel()
{
    int c = blockIdx.x & 15;
    int h = blockIdx.x >> 4;
    int d = threadIdx.x;
    float sum = 0.f, mx = -INFINITY;
    for (int r = 0; r < CS; r++) {
        float v = g_k[(size_t)(c * CS + r) * (HKV * HD) + h * HD + d];
        sum += v;
        mx = fmaxf(mx, v);
    }
    g_kcmean[(h * NC + c) * HD + d] = sum * (1.f / CS);
    g_kcmax [(h * NC + c) * HD + d] = mx;
}

__device__ __forceinline__ float warpsum(float v)
{
    #pragma unroll
    for (int o = 16; o; o >>= 1) v += __shfl_xor_sync(0xffffffffu, v, o);
    return v;
}
__device__ __forceinline__ float warpmax(float v)
{
    #pragma unroll
    for (int o = 16; o; o >>= 1) v = fmaxf(v, __shfl_xor_sync(0xffffffffu, v, o));
    return v;
}

// ---------------- block scores + top-8 selection (warp per (h,q)) ----------
__global__ __launch_bounds__(256) void score_kernel()
{
    int w = blockIdx.x * 8 + (threadIdx.x >> 5);
    int lane = threadIdx.x & 31;
    int h = w >> 11;
    int q = w & 2047;

    float qv[G_GRP][4];
    #pragma unroll
    for (int g = 0; g < G_GRP; g++)
        #pragma unroll
        for (int j = 0; j < 4; j++)
            qv[g][j] = g_q[(size_t)q * (HQ * HD) + (h * G_GRP + g) * HD + lane + 32 * j];

    int qblk = q >> 7;
    float score[NC];
    for (int c = 0; c < NC; c++) {
        if (c > qblk) { score[c] = NEGV; continue; }
        float pm[G_GRP], px[G_GRP];
        #pragma unroll
        for (int g = 0; g < G_GRP; g++) { pm[g] = 0.f; px[g] = 0.f; }
        #pragma unroll
        for (int j = 0; j < 4; j++) {
            float km = g_kcmean[(h * NC + c) * HD + lane + 32 * j];
            float kx = g_kcmax [(h * NC + c) * HD + lane + 32 * j];
            #pragma unroll
            for (int g = 0; g < G_GRP; g++) { pm[g] += qv[g][j] * km; px[g] += qv[g][j] * kx; }
        }
        float meanv = 0.f, maxv = -INFINITY;
        #pragma unroll
        for (int g = 0; g < G_GRP; g++) {
            float a = warpsum(pm[g]);
            float b = warpsum(px[g]);
            float sg = SCALE * (MIXL * a + (1.f - MIXL) * b);
            meanv += sg;
            maxv = fmaxf(maxv, sg);
        }
        score[c] = ALPHA * (meanv * (1.f / G_GRP)) + (1.f - ALPHA) * maxv;
    }

    unsigned sel = 0;
    int nsel = min(NBLK, qblk + 1);
    for (int it = 0; it < nsel; it++) {
        float best = -INFINITY; int bi = 0;
        for (int c = 0; c <= qblk; c++)
            if (!((sel >> c) & 1) && score[c] > best) { best = score[c]; bi = c; }
        sel |= 1u << bi;
    }
    if (lane == 0) g_sel[h * S + q] = sel;
}

// ---------------- block-sparse flash attention (warp per (h,q)) ------------
// Key-parallel: each lane owns one key of a 32-key chunk.
__global__ __launch_bounds__(256) void attn_kernel(const int* __restrict__ am)
{
    __shared__ float sq[8][HD];
    int wslot = threadIdx.x >> 5;
    int w = blockIdx.x * 8 + wslot;
    int lane = threadIdx.x & 31;
    int h = w >> 11;
    int q = w & 2047;
    int kvh = h >> 3;

    #pragma unroll
    for (int j = 0; j < 4; j++)
        sq[wslot][lane + 32 * j] = g_q[(size_t)q * (HQ * HD) + h * HD + lane + 32 * j];
    __syncwarp();

    const float* kT = g_kT + (size_t)kvh * HD * S;
    unsigned sel = g_sel[kvh * S + q];
    int qblk = q >> 7;

    float m = -INFINITY, l = 0.f;
    float acc[4] = {0.f, 0.f, 0.f, 0.f};

    for (int c = 0; c <= qblk; c++) {
        int lo = c << 7;
        int hi = min(lo + CS - 1, q);
        if (!((sel >> c) & 1)) lo = max(lo, q - (WIN - 1));
        if (lo > hi) continue;
        for (int base = lo & ~31; base <= hi; base += 32) {
            int key = base + lane;
            bool valid = (key >= lo) && (key <= hi) && (am[key & (S - 1)] > 0);

            // QK dot: lane-per-key, coalesced along s in kT
            float dot = 0.f;
            const float* kc = kT + base + lane;   // padded array; OOB lanes read pad zeros
            #pragma unroll 8
            for (int d = 0; d < HD; d++)
                dot += sq[wslot][d] * kc[(size_t)d * S];

            float logit = valid ? dot * SCALE : -INFINITY;

            // online softmax, batched per chunk
            float cmax = warpmax(logit);
            float nm = fmaxf(m, cmax);
            float r = __expf(m - nm);          // m=-inf initially -> r=0
            l *= r;
            acc[0] *= r; acc[1] *= r; acc[2] *= r; acc[3] *= r;
            float p = __expf(logit - nm);      // invalid -> exp(-inf)=0
            l += warpsum(p);
            m = nm;

            // PV: broadcast p_j, coalesced V row loads
            const float* vb = g_v + (size_t)base * (HKV * HD) + kvh * HD + lane;
            #pragma unroll 4
            for (int j = 0; j < 32; j++) {
                float pj = __shfl_sync(0xffffffffu, p, j);
                const float* vr = vb + (size_t)j * (HKV * HD);
                acc[0] += pj * vr[0];
                acc[1] += pj * vr[32];
                acc[2] += pj * vr[64];
                acc[3] += pj * vr[96];
            }
        }
    }
    float inv = 1.f / l;
    #pragma unroll
    for (int j = 0; j < 4; j++)
        g_attn[(size_t)q * (HQ * HD) + h * HD + lane + 32 * j] = acc[j] * inv;
}

// ---------------- launch ----------------------------------------------------
extern "C" void kernel_launch(void* const* d_in, const int* in_sizes, int n_in,
                              void* d_out, int out_size)
{
    const float* hs   = (const float*)d_in[0];
    const float* cosb = (const float*)d_in[1];
    const float* sinb = (const float*)d_in[2];
    const int*   am   = (const int*)d_in[3];
    const float* Wq = (const float*)d_in[5];
    const float* bq = (const float*)d_in[6];
    const float* Wk = (const float*)d_in[7];
    const float* bk = (const float*)d_in[8];
    const float* Wv = (const float*)d_in[9];
    const float* bv = (const float*)d_in[10];
    const float* Wo = (const float*)d_in[11];
    float* out = (float*)d_out;

    float *pq, *pk, *pv, *pattn;
    cudaGetSymbolAddress((void**)&pq, g_q);
    cudaGetSymbolAddress((void**)&pk, g_k);
    cudaGetSymbolAddress((void**)&pv, g_v);
    cudaGetSymbolAddress((void**)&pattn, g_attn);

    // projections (3xTF32 tensor cores, ~fp32 accuracy)
    gemm_3xtf32<<<dim3(HQ * HD / GBN, S / GBM), 256>>>(hs, Wq, bq, pq, S, HQ * HD, HID);
    gemm_3xtf32<<<dim3(HKV * HD / GBN, S / GBM), 256>>>(hs, Wk, bk, pk, S, HKV * HD, HID);
    gemm_3xtf32<<<dim3(HKV * HD / GBN, S / GBM), 256>>>(hs, Wv, bv, pv, S, HKV * HD, HID);

    // rope
    rope_kernel<<<(S * HQ * 64 + 255) / 256, 256>>>(pq, cosb, sinb, HQ, HQ * HD);
    rope_kernel<<<(S * HKV * 64 + 255) / 256, 256>>>(pk, cosb, sinb, HKV, HKV * HD);

    // K transpose (after rope)
    transpose_k<<<dim3(S / 32, HD / 32, HKV), 256>>>();

    // chunk stats + selection
    blockstats_kernel<<<HKV * NC, HD>>>();
    score_kernel<<<HKV * S / 8, 256>>>();

    // sparse attention
    attn_kernel<<<HQ * S / 8, 256>>>(am);

    // output projection (no bias)
    gemm_3xtf32<<<dim3(HID / GBN, S / GBM), 256>>>(pattn, Wo, nullptr, out, S, HID, HQ * HD);
}

// round 10
// speedup vs baseline: 1.4508x; 1.4508x over previous
#include <cuda_runtime.h>
#include <math.h>
#include <stdint.h>

#define S 2048
#define HID 2048
#define HQ 16
#define HKV 2
#define HD 128
#define G_GRP 8          // HQ / HKV
#define CS 128
#define NC 16            // S / CS
#define WIN 16
#define NBLK 8           // BUDGET / CS
#define ALPHA 0.8f
#define MIXL 0.5f
#define SCALE 0.08838834764831845f  // 128^-0.5
#define NEGV -1000000000.0f

// ---------------- scratch (device globals; no allocation allowed) ----------
__device__ float g_q[S * HQ * HD];            // [s][h*128+d]
__device__ float g_k[S * HKV * HD];           // [s][h*128+d]
__device__ float g_kT[HKV * HD * S + 64];     // [kvh][d][s]
__device__ float g_v[S * HKV * HD + 32 * HKV * HD];
__device__ float g_kcmean[HKV * NC * HD];
__device__ float g_kcmax[HKV * NC * HD];
__device__ unsigned g_sel[HKV * S];
__device__ float g_attn[S * HQ * HD];         // [s][h*128+d]

// ---------------- 3xTF32 tensor-core GEMM ----------------------------------
#define GBM 128
#define GBN 128
#define GBK 16
#define ASTR 132
#define BSTR 132

__device__ __forceinline__ uint32_t f2tf32(float f)
{
    uint32_t r;
    asm("cvt.rna.tf32.f32 %0, %1;" : "=r"(r) : "f"(f));
    return r;
}

__device__ __forceinline__ void split_tf32(float x, uint32_t& h, uint32_t& l)
{
    h = f2tf32(x);
    l = f2tf32(x - __uint_as_float(h));
}

__device__ __forceinline__ void mma_tf32(float c[4], const uint32_t a[4], const uint32_t b[2])
{
    asm volatile(
        "mma.sync.aligned.m16n8k8.row.col.f32.tf32.tf32.f32 "
        "{%0,%1,%2,%3}, {%4,%5,%6,%7}, {%8,%9}, {%0,%1,%2,%3};"
        : "+f"(c[0]), "+f"(c[1]), "+f"(c[2]), "+f"(c[3])
        : "r"(a[0]), "r"(a[1]), "r"(a[2]), "r"(a[3]), "r"(b[0]), "r"(b[1]));
}

__global__ __launch_bounds__(256) void gemm_3xtf32(
    const float* __restrict__ A, const float* __restrict__ B,
    const float* __restrict__ bias, float* __restrict__ C,
    int M, int N, int K)
{
    __shared__ uint32_t AsH[GBK][ASTR];
    __shared__ uint32_t AsL[GBK][ASTR];
    __shared__ uint32_t BsH[GBK][BSTR];
    __shared__ uint32_t BsL[GBK][BSTR];

    int tid = threadIdx.x;
    int lane = tid & 31;
    int wid = tid >> 5;
    int wm = (wid & 3) * 32;
    int wn = (wid >> 2) * 64;

    const float* Ab = A + (size_t)blockIdx.y * GBM * K;
    const float* Bb = B + (size_t)blockIdx.x * GBN;

    int ar = tid >> 2;
    int ak = (tid & 3) * 4;
    int bkr = tid >> 5;
    int bn = (tid & 31) * 4;

    float4 ra0, ra1, rb0, rb1;
    ra0 = *(const float4*)(Ab + (size_t)ar * K + ak);
    ra1 = *(const float4*)(Ab + (size_t)(ar + 64) * K + ak);
    rb0 = *(const float4*)(Bb + (size_t)bkr * N + bn);
    rb1 = *(const float4*)(Bb + (size_t)(bkr + 8) * N + bn);

    float acc[2][8][4];
    #pragma unroll
    for (int mt = 0; mt < 2; mt++)
        #pragma unroll
        for (int nt = 0; nt < 8; nt++)
            #pragma unroll
            for (int c = 0; c < 4; c++) acc[mt][nt][c] = 0.f;

    int qrow = lane >> 2;
    int qcol = lane & 3;

    for (int k0 = 0; k0 < K; k0 += GBK) {
        {
            uint32_t h, l;
            split_tf32(ra0.x, h, l); AsH[ak + 0][ar] = h; AsL[ak + 0][ar] = l;
            split_tf32(ra0.y, h, l); AsH[ak + 1][ar] = h; AsL[ak + 1][ar] = l;
            split_tf32(ra0.z, h, l); AsH[ak + 2][ar] = h; AsL[ak + 2][ar] = l;
            split_tf32(ra0.w, h, l); AsH[ak + 3][ar] = h; AsL[ak + 3][ar] = l;
            split_tf32(ra1.x, h, l); AsH[ak + 0][ar + 64] = h; AsL[ak + 0][ar + 64] = l;
            split_tf32(ra1.y, h, l); AsH[ak + 1][ar + 64] = h; AsL[ak + 1][ar + 64] = l;
            split_tf32(ra1.z, h, l); AsH[ak + 2][ar + 64] = h; AsL[ak + 2][ar + 64] = l;
            split_tf32(ra1.w, h, l); AsH[ak + 3][ar + 64] = h; AsL[ak + 3][ar + 64] = l;
            split_tf32(rb0.x, h, l); BsH[bkr][bn + 0] = h; BsL[bkr][bn + 0] = l;
            split_tf32(rb0.y, h, l); BsH[bkr][bn + 1] = h; BsL[bkr][bn + 1] = l;
            split_tf32(rb0.z, h, l); BsH[bkr][bn + 2] = h; BsL[bkr][bn + 2] = l;
            split_tf32(rb0.w, h, l); BsH[bkr][bn + 3] = h; BsL[bkr][bn + 3] = l;
            split_tf32(rb1.x, h, l); BsH[bkr + 8][bn + 0] = h; BsL[bkr + 8][bn + 0] = l;
            split_tf32(rb1.y, h, l); BsH[bkr + 8][bn + 1] = h; BsL[bkr + 8][bn + 1] = l;
            split_tf32(rb1.z, h, l); BsH[bkr + 8][bn + 2] = h; BsL[bkr + 8][bn + 2] = l;
            split_tf32(rb1.w, h, l); BsH[bkr + 8][bn + 3] = h; BsL[bkr + 8][bn + 3] = l;
        }
        __syncthreads();

        if (k0 + GBK < K) {
            ra0 = *(const float4*)(Ab + (size_t)ar * K + (k0 + GBK) + ak);
            ra1 = *(const float4*)(Ab + (size_t)(ar + 64) * K + (k0 + GBK) + ak);
            rb0 = *(const float4*)(Bb + (size_t)(k0 + GBK + bkr) * N + bn);
            rb1 = *(const float4*)(Bb + (size_t)(k0 + GBK + bkr + 8) * N + bn);
        }

        #pragma unroll
        for (int ks = 0; ks < 2; ks++) {
            int kb = ks * 8;
            uint32_t afH[2][4], afL[2][4];
            #pragma unroll
            for (int mt = 0; mt < 2; mt++) {
                int mb = wm + mt * 16;
                afH[mt][0] = AsH[kb + qcol][mb + qrow];
                afH[mt][1] = AsH[kb + qcol][mb + qrow + 8];
                afH[mt][2] = AsH[kb + qcol + 4][mb + qrow];
                afH[mt][3] = AsH[kb + qcol + 4][mb + qrow + 8];
                afL[mt][0] = AsL[kb + qcol][mb + qrow];
                afL[mt][1] = AsL[kb + qcol][mb + qrow + 8];
                afL[mt][2] = AsL[kb + qcol + 4][mb + qrow];
                afL[mt][3] = AsL[kb + qcol + 4][mb + qrow + 8];
            }
            uint32_t bfH[8][2], bfL[8][2];
            #pragma unroll
            for (int nt = 0; nt < 8; nt++) {
                int nb = wn + nt * 8;
                bfH[nt][0] = BsH[kb + qcol][nb + qrow];
                bfH[nt][1] = BsH[kb + qcol + 4][nb + qrow];
                bfL[nt][0] = BsL[kb + qcol][nb + qrow];
                bfL[nt][1] = BsL[kb + qcol + 4][nb + qrow];
            }
            #pragma unroll
            for (int mt = 0; mt < 2; mt++)
                #pragma unroll
                for (int nt = 0; nt < 8; nt++) {
                    mma_tf32(acc[mt][nt], afL[mt], bfH[nt]);
                    mma_tf32(acc[mt][nt], afH[mt], bfL[nt]);
                    mma_tf32(acc[mt][nt], afH[mt], bfH[nt]);
                }
        }
        __syncthreads();
    }

    #pragma unroll
    for (int mt = 0; mt < 2; mt++) {
        int row0 = blockIdx.y * GBM + wm + mt * 16 + qrow;
        #pragma unroll
        for (int nt = 0; nt < 8; nt++) {
            int col = blockIdx.x * GBN + wn + nt * 8 + qcol * 2;
            float b0 = 0.f, b1 = 0.f;
            if (bias) { b0 = bias[col]; b1 = bias[col + 1]; }
            float2 o0 = make_float2(acc[mt][nt][0] + b0, acc[mt][nt][1] + b1);
            float2 o1 = make_float2(acc[mt][nt][2] + b0, acc[mt][nt][3] + b1);
            *(float2*)(C + (size_t)row0 * N + col) = o0;
            *(float2*)(C + (size_t)(row0 + 8) * N + col) = o1;
        }
    }
}

// ---------------- RoPE -----------------------------------------------------
__global__ void rope_kernel(float* __restrict__ x, const float* __restrict__ cosb,
                            const float* __restrict__ sinb, int H, int stride)
{
    int idx = blockIdx.x * blockDim.x + threadIdx.x;
    if (idx >= S * H * 64) return;
    int d = idx & 63;
    int h = (idx >> 6) % H;
    int s = idx / (64 * H);
    float c0 = cosb[s * HD + d],      s0 = sinb[s * HD + d];
    float c1 = cosb[s * HD + d + 64], s1 = sinb[s * HD + d + 64];
    float* p = x + (size_t)s * stride + h * HD;
    float x0 = p[d], x1 = p[d + 64];
    p[d]      = x0 * c0 - x1 * s0;
    p[d + 64] = x1 * c1 + x0 * s1;
}

// ---------------- K transpose: g_kT[kvh][d][s] = g_k[s][kvh*HD+d] ----------
__global__ __launch_bounds__(256) void transpose_k()
{
    __shared__ float t[32][33];
    int kvh = blockIdx.z;
    int s0 = blockIdx.x * 32, d0 = blockIdx.y * 32;
    int x = threadIdx.x & 31, y0 = threadIdx.x >> 5;
    #pragma unroll
    for (int yy = y0; yy < 32; yy += 8)
        t[yy][x] = g_k[(size_t)(s0 + yy) * (HKV * HD) + kvh * HD + d0 + x];
    __syncthreads();
    #pragma unroll
    for (int yy = y0; yy < 32; yy += 8)
        g_kT[(size_t)kvh * HD * S + (size_t)(d0 + yy) * S + s0 + x] = t[x][yy];
}

// ---------------- per-chunk K stats ----------------------------------------
__global__ void blockstats_kernel()
{
    int c = blockIdx.x & 15;
    int h = blockIdx.x >> 4;
    int d = threadIdx.x;
    float sum = 0.f, mx = -INFINITY;
    for (int r = 0; r < CS; r++) {
        float v = g_k[(size_t)(c * CS + r) * (HKV * HD) + h * HD + d];
        sum += v;
        mx = fmaxf(mx, v);
    }
    g_kcmean[(h * NC + c) * HD + d] = sum * (1.f / CS);
    g_kcmax [(h * NC + c) * HD + d] = mx;
}

__device__ __forceinline__ float warpsum(float v)
{
    #pragma unroll
    for (int o = 16; o; o >>= 1) v += __shfl_xor_sync(0xffffffffu, v, o);
    return v;
}
__device__ __forceinline__ float warpmax(float v)
{
    #pragma unroll
    for (int o = 16; o; o >>= 1) v = fmaxf(v, __shfl_xor_sync(0xffffffffu, v, o));
    return v;
}

// ---------------- block scores + top-8 selection (warp per (h,q)) ----------
__global__ __launch_bounds__(256) void score_kernel()
{
    int w = blockIdx.x * 8 + (threadIdx.x >> 5);
    int lane = threadIdx.x & 31;
    int h = w >> 11;
    int q = w & 2047;

    float qv[G_GRP][4];
    #pragma unroll
    for (int g = 0; g < G_GRP; g++)
        #pragma unroll
        for (int j = 0; j < 4; j++)
            qv[g][j] = g_q[(size_t)q * (HQ * HD) + (h * G_GRP + g) * HD + lane + 32 * j];

    int qblk = q >> 7;
    float score[NC];
    for (int c = 0; c < NC; c++) {
        if (c > qblk) { score[c] = NEGV; continue; }
        float pm[G_GRP], px[G_GRP];
        #pragma unroll
        for (int g = 0; g < G_GRP; g++) { pm[g] = 0.f; px[g] = 0.f; }
        #pragma unroll
        for (int j = 0; j < 4; j++) {
            float km = g_kcmean[(h * NC + c) * HD + lane + 32 * j];
            float kx = g_kcmax [(h * NC + c) * HD + lane + 32 * j];
            #pragma unroll
            for (int g = 0; g < G_GRP; g++) { pm[g] += qv[g][j] * km; px[g] += qv[g][j] * kx; }
        }
        float meanv = 0.f, maxv = -INFINITY;
        #pragma unroll
        for (int g = 0; g < G_GRP; g++) {
            float a = warpsum(pm[g]);
            float b = warpsum(px[g]);
            float sg = SCALE * (MIXL * a + (1.f - MIXL) * b);
            meanv += sg;
            maxv = fmaxf(maxv, sg);
        }
        score[c] = ALPHA * (meanv * (1.f / G_GRP)) + (1.f - ALPHA) * maxv;
    }

    unsigned sel = 0;
    int nsel = min(NBLK, qblk + 1);
    for (int it = 0; it < nsel; it++) {
        float best = -INFINITY; int bi = 0;
        for (int c = 0; c <= qblk; c++)
            if (!((sel >> c) & 1) && score[c] > best) { best = score[c]; bi = c; }
        sel |= 1u << bi;
    }
    if (lane == 0) g_sel[h * S + q] = sel;
}

// ---------------- block-sparse attention: warp per (kvh,q), 8 heads --------
// K element loaded once -> 8 FFMAs (all GQA heads); V row loaded once -> 32.
__global__ __launch_bounds__(256) void attn_kernel(const int* __restrict__ am)
{
    __shared__ float sq[8][HD][G_GRP];   // [warp][d][g]  32KB
    int wslot = threadIdx.x >> 5;
    int lane = threadIdx.x & 31;
    int w = blockIdx.x * 8 + wslot;      // 0 .. HKV*S-1
    int kvh = w >> 11;
    int idx = w & 2047;
    // balance: pair small-q with large-q so blocks carry ~equal work
    int q = (idx & 1) ? (S - 1 - (idx >> 1)) : (idx >> 1);

    // stage 8 heads' q rows: [d][g] layout for LDS.128 broadcast
    #pragma unroll
    for (int j = 0; j < 32; j++) {
        int i = lane + 32 * j;           // 0..1023
        int g = i >> 7, d = i & 127;
        sq[wslot][d][g] = g_q[(size_t)q * (HQ * HD) + (kvh * G_GRP + g) * HD + d];
    }
    __syncwarp();

    const float* kT = g_kT + (size_t)kvh * HD * S;
    unsigned sel = g_sel[kvh * S + q];
    int qblk = q >> 7;

    float m[G_GRP], l[G_GRP], acc[G_GRP][4];
    #pragma unroll
    for (int g = 0; g < G_GRP; g++) {
        m[g] = -INFINITY; l[g] = 0.f;
        acc[g][0] = acc[g][1] = acc[g][2] = acc[g][3] = 0.f;
    }

    for (int c = 0; c <= qblk; c++) {
        int lo = c << 7;
        int hi = min(lo + CS - 1, q);
        if (!((sel >> c) & 1)) lo = max(lo, q - (WIN - 1));
        if (lo > hi) continue;
        for (int base = lo & ~31; base <= hi; base += 32) {
            int key = base + lane;
            bool valid = (key >= lo) && (key <= hi) && (am[key] > 0);

            // QK: lane owns one key; each K value feeds 8 head-dots
            float dot[G_GRP];
            #pragma unroll
            for (int g = 0; g < G_GRP; g++) dot[g] = 0.f;
            const float* kp = kT + base + lane;
            const float4* qv4 = (const float4*)&sq[wslot][0][0];
            #pragma unroll 8
            for (int d = 0; d < HD; d++) {
                float kv = *kp;
                kp += S;
                float4 qa = qv4[0];
                float4 qb = qv4[1];
                qv4 += 2;
                dot[0] += qa.x * kv; dot[1] += qa.y * kv;
                dot[2] += qa.z * kv; dot[3] += qa.w * kv;
                dot[4] += qb.x * kv; dot[5] += qb.y * kv;
                dot[6] += qb.z * kv; dot[7] += qb.w * kv;
            }

            // chunk-batched online softmax per head
            float p[G_GRP];
            #pragma unroll
            for (int g = 0; g < G_GRP; g++) {
                float logit = valid ? dot[g] * SCALE : -INFINITY;
                float cmax = warpmax(logit);
                float nm = fmaxf(m[g], cmax);
                float r = __expf(m[g] - nm);
                l[g] *= r;
                acc[g][0] *= r; acc[g][1] *= r; acc[g][2] *= r; acc[g][3] *= r;
                p[g] = __expf(logit - nm);
                l[g] += warpsum(p[g]);
                m[g] = nm;
            }

            // PV: V row loaded once, feeds 8 heads
            const float* vr = g_v + (size_t)base * (HKV * HD) + kvh * HD + lane;
            #pragma unroll 4
            for (int j = 0; j < 32; j++) {
                float v0 = vr[0], v1 = vr[32], v2 = vr[64], v3 = vr[96];
                #pragma unroll
                for (int g = 0; g < G_GRP; g++) {
                    float pj = __shfl_sync(0xffffffffu, p[g], j);
                    acc[g][0] += pj * v0;
                    acc[g][1] += pj * v1;
                    acc[g][2] += pj * v2;
                    acc[g][3] += pj * v3;
                }
                vr += HKV * HD;
            }
        }
    }

    #pragma unroll
    for (int g = 0; g < G_GRP; g++) {
        float inv = 1.f / l[g];
        #pragma unroll
        for (int i = 0; i < 4; i++)
            g_attn[(size_t)q * (HQ * HD) + (kvh * G_GRP + g) * HD + lane + 32 * i] =
                acc[g][i] * inv;
    }
}

// ---------------- launch ----------------------------------------------------
extern "C" void kernel_launch(void* const* d_in, const int* in_sizes, int n_in,
                              void* d_out, int out_size)
{
    const float* hs   = (const float*)d_in[0];
    const float* cosb = (const float*)d_in[1];
    const float* sinb = (const float*)d_in[2];
    const int*   am   = (const int*)d_in[3];
    const float* Wq = (const float*)d_in[5];
    const float* bq = (const float*)d_in[6];
    const float* Wk = (const float*)d_in[7];
    const float* bk = (const float*)d_in[8];
    const float* Wv = (const float*)d_in[9];
    const float* bv = (const float*)d_in[10];
    const float* Wo = (const float*)d_in[11];
    float* out = (float*)d_out;

    float *pq, *pk, *pv, *pattn;
    cudaGetSymbolAddress((void**)&pq, g_q);
    cudaGetSymbolAddress((void**)&pk, g_k);
    cudaGetSymbolAddress((void**)&pv, g_v);
    cudaGetSymbolAddress((void**)&pattn, g_attn);

    // projections (3xTF32 tensor cores, ~fp32 accuracy)
    gemm_3xtf32<<<dim3(HQ * HD / GBN, S / GBM), 256>>>(hs, Wq, bq, pq, S, HQ * HD, HID);
    gemm_3xtf32<<<dim3(HKV * HD / GBN, S / GBM), 256>>>(hs, Wk, bk, pk, S, HKV * HD, HID);
    gemm_3xtf32<<<dim3(HKV * HD / GBN, S / GBM), 256>>>(hs, Wv, bv, pv, S, HKV * HD, HID);

    // rope
    rope_kernel<<<(S * HQ * 64 + 255) / 256, 256>>>(pq, cosb, sinb, HQ, HQ * HD);
    rope_kernel<<<(S * HKV * 64 + 255) / 256, 256>>>(pk, cosb, sinb, HKV, HKV * HD);

    // K transpose (after rope)
    transpose_k<<<dim3(S / 32, HD / 32, HKV), 256>>>();

    // chunk stats + selection
    blockstats_kernel<<<HKV * NC, HD>>>();
    score_kernel<<<HKV * S / 8, 256>>>();

    // sparse attention: warp per (kvh,q), 8 heads per warp
    attn_kernel<<<HKV * S / 8, 256>>>(am);

    // output projection (no bias)
    gemm_3xtf32<<<dim3(HID / GBN, S / GBM), 256>>>(pattn, Wo, nullptr, out, S, HID, HQ * HD);
}